// round 13
// baseline (speedup 1.0000x reference)
#include <cuda_runtime.h>
#include <math.h>

#define EC_MAX 64
#define BLK 256
#define PPB 128          // points per block (threads 0-127 -> e low half, 128-255 -> high)
#define MAX_BLOCKS 8192

__device__ float g_pen_part[MAX_BLOCKS];
__device__ int   g_ctr = 0;          // last-block-done counter (reset each replay)

#define LOG2E 1.4426950408889634f

// sigmoid via single HW MUFU tanh: sigma(x) = 0.5*tanh(x/2) + 0.5
__device__ __forceinline__ float fsig_times(float rbf, float x, float acc) {
    float t;
    asm("tanh.approx.f32 %0, %1;" : "=f"(t) : "f"(x * 0.5f));
    return fmaf(rbf, fmaf(t, 0.5f, 0.5f), acc);
}

__device__ __forceinline__ float fexp2(float x) {
    float r;
    asm("ex2.approx.f32 %0, %1;" : "=f"(r) : "f"(x));
    return r;
}

// Per-element packed coefficients (scale s=-0.5*log2e folded into A), 3 float4/elt:
//  p0 = {cx, cy, cz, w0}   p1 = {a00, a01, a02, a11}   p2 = {a12, a22, -, -}
// rbf = exp2( dx^T a dx + w0 ),  d = p - c,  w0 = log2|const|
__device__ __forceinline__ void compute_params(
    float4* sp, int ec,
    const float* __restrict__ constants,
    const float* __restrict__ centers,
    const float* __restrict__ radii,
    const float* __restrict__ rotations)
{
    int e = threadIdx.x;
    if (e < ec) {
        float ccx = centers[3*e+0];
        float ccy = centers[3*e+1];
        float ccz = centers[3*e+2];
        float cab = fabsf(constants[e]);
        float d0 = __fdividef(1.0f, fabsf(radii[3*e+0]) + 0.005f + 1e-8f);
        float d1 = __fdividef(1.0f, fabsf(radii[3*e+1]) + 0.005f + 1e-8f);
        float d2 = __fdividef(1.0f, fabsf(radii[3*e+2]) + 0.005f + 1e-8f);

        float sx, cx, sy, cy, sz, cz;
        __sincosf(rotations[3*e+0], &sx, &cx);
        __sincosf(rotations[3*e+1], &sy, &cy);
        __sincosf(rotations[3*e+2], &sz, &cz);

        float R00 = cz * cy;
        float R01 = cz * sy * sx - sz * cx;
        float R02 = cz * sy * cx + sz * sx;
        float R10 = sz * cy;
        float R11 = sz * sy * sx + cz * cx;
        float R12 = sz * sy * cx - cz * sx;
        float R20 = -sy;
        float R21 = cy * sx;
        float R22 = cy * cx;

        float c00 = R00*R00*d0 + R01*R01*d1 + R02*R02*d2;
        float c01 = R00*R10*d0 + R01*R11*d1 + R02*R12*d2;
        float c02 = R00*R20*d0 + R01*R21*d1 + R02*R22*d2;
        float c11 = R10*R10*d0 + R11*R11*d1 + R12*R12*d2;
        float c12 = R10*R20*d0 + R11*R21*d1 + R12*R22*d2;
        float c22 = R20*R20*d0 + R21*R21*d1 + R22*R22*d2;

        const float s = -0.5f * LOG2E;
        float w0 = __log2f(cab);

        sp[e*3 + 0] = make_float4(ccx, ccy, ccz, w0);
        sp[e*3 + 1] = make_float4(s*c00, s*c01, s*c02, s*c11);
        sp[e*3 + 2] = make_float4(s*c12, s*c22, 0.0f, 0.0f);
    }
}

__global__ void __launch_bounds__(BLK, 8) rbf_main(
    const float* __restrict__ wsp,
    const float4* __restrict__ act,
    const float* __restrict__ dists,
    float4* __restrict__ out,
    const float* __restrict__ constants,
    const float* __restrict__ centers,
    const float* __restrict__ radii,
    const float* __restrict__ rotations,
    int N, int ec, int out_size)
{
    __shared__ float4 sp[EC_MAX * 3];
    __shared__ float s_sum[PPB];
    __shared__ float4 s_acc[PPB];
    __shared__ float wpen[BLK / 32];
    __shared__ bool s_last;

    int tid = threadIdx.x;
    compute_params(sp, ec, constants, centers, radii, rotations);
    __syncthreads();

    int pt   = tid & (PPB - 1);          // 0..127: which point in the block
    int half = tid >> 7;                 // 0 or 1: which element half
    int n = blockIdx.x * PPB + pt;
    bool valid = n < N;

    int ehalf = ec >> 1;                 // 32
    int e0 = half * ehalf;

    float px=0, py=0, pz=0, ndl=0;
    if (valid) {
        px = wsp[3*n+0];
        py = wsp[3*n+1];
        pz = wsp[3*n+2];
        ndl = -dists[n] * LOG2E;         // alpha = 1 - exp2(relu(aw)*ndl)
    }

    float sum = 0.0f, ax = 0.0f, ay = 0.0f, az = 0.0f, aw = 0.0f;
    float pen = 0.0f;

    const float4* col = act + (size_t)e0 * N + n;
    const float4* cf  = sp + e0 * 3;

    #pragma unroll 2
    for (int e = 0; e < ehalf; ++e) {
        float4 p0 = cf[0];
        float4 p1 = cf[1];
        float4 p2 = cf[2];
        cf += 3;

        float4 a = valid ? __ldcs(col) : make_float4(0,0,0,0);
        col += N;

        float dx = px - p0.x, dy = py - p0.y, dz = pz - p0.z;
        float tx = fmaf(p1.x, dx, fmaf(p1.y, dy, p1.z * dz));
        float ty = fmaf(p1.y, dx, fmaf(p1.w, dy, p2.x * dz));
        float tz = fmaf(p1.z, dx, fmaf(p2.x, dy, p2.y * dz));
        float t  = fmaf(dx, tx, fmaf(dy, ty, fmaf(dz, tz, p0.w)));
        float rbf = fexp2(t);

        sum += rbf;
        pen += fmaxf(rbf - 0.01f, 0.0f);

        float alpha = 1.0f - fexp2(fmaxf(a.w, 0.0f) * ndl);
        ax = fsig_times(rbf, a.x, ax);
        ay = fsig_times(rbf, a.y, ay);
        az = fsig_times(rbf, a.z, az);
        aw = fmaf(rbf, alpha, aw);
    }

    // high half publishes its partials; low half combines, normalizes, stores
    if (half == 1) {
        s_sum[pt] = sum;
        s_acc[pt] = make_float4(ax, ay, az, aw);
    }
    __syncthreads();
    if (half == 0 && valid) {
        float4 o = s_acc[pt];
        float st = sum + s_sum[pt];
        float winv = __fdividef(1.0f, st + 1e-6f);
        out[n] = make_float4((ax + o.x)*winv, (ay + o.y)*winv,
                             (az + o.z)*winv, (aw + o.w)*winv);
    }

    // block penalty reduction (both halves contribute)
    #pragma unroll
    for (int off = 16; off; off >>= 1)
        pen += __shfl_xor_sync(0xffffffffu, pen, off);
    if ((tid & 31) == 0) wpen[tid >> 5] = pen;
    __syncthreads();
    if (tid == 0) {
        float s = 0.0f;
        #pragma unroll
        for (int w = 0; w < BLK / 32; ++w) s += wpen[w];
        g_pen_part[blockIdx.x] = s;
        __threadfence();
        int done = atomicAdd(&g_ctr, 1);
        s_last = (done == (int)gridDim.x - 1);
    }
    __syncthreads();

    // last finished block reduces all partials + bbox penalty, writes scalar,
    // resets counter for deterministic graph replay.
    if (s_last) {
        float s = 0.0f;
        for (int i = tid; i < (int)gridDim.x; i += BLK) s += g_pen_part[i];
        if (tid < ec) {
            float cx0 = centers[3*tid+0], cy0 = centers[3*tid+1], cz0 = centers[3*tid+2];
            float bp = fmaxf(cx0 - 0.6f, 0.0f) + fmaxf(-0.6f  - cx0, 0.0f)
                     + fmaxf(cy0 - 0.6f, 0.0f) + fmaxf(-0.6f  - cy0, 0.0f)
                     + fmaxf(cz0 - 0.6f, 0.0f) + fmaxf(-0.35f - cz0, 0.0f);
            s += bp * (float)N * 1000.0f;   // undo the 0.001/N scale below
        }
        #pragma unroll
        for (int off = 16; off; off >>= 1)
            s += __shfl_xor_sync(0xffffffffu, s, off);
        if ((tid & 31) == 0) wpen[tid >> 5] = s;
        __syncthreads();
        if (tid == 0) {
            float tot = 0.0f;
            #pragma unroll
            for (int w = 0; w < BLK / 32; ++w) tot += wpen[w];
            if (out_size > 4 * N)
                ((float*)out)[out_size - 1] = 0.001f * tot / (float)N;
            g_ctr = 0;
        }
    }
}

extern "C" void kernel_launch(void* const* d_in, const int* in_sizes, int n_in,
                              void* d_out, int out_size) {
    const float*  wsp       = (const float*)d_in[0];
    const float4* act       = (const float4*)d_in[1];
    const float*  dists     = (const float*)d_in[2];
    const float*  constants = (const float*)d_in[3];
    const float*  centers   = (const float*)d_in[4];
    const float*  radii     = (const float*)d_in[5];
    const float*  rotations = (const float*)d_in[6];

    int N  = in_sizes[0] / 3;
    int ec = in_sizes[3];
    if (ec > EC_MAX) ec = EC_MAX;

    int blocks = (N + PPB - 1) / PPB;
    if (blocks > MAX_BLOCKS) blocks = MAX_BLOCKS;  // N fits for this problem
    rbf_main<<<blocks, BLK>>>(wsp, act, dists, (float4*)d_out,
                              constants, centers, radii, rotations, N, ec, out_size);
}

// round 15
// speedup vs baseline: 1.0304x; 1.0304x over previous
#include <cuda_runtime.h>
#include <math.h>

#define EC_MAX 64
#define BLK 256
#define PPB 128          // points per tile (threads 0-127 -> e low half, 128-255 -> high)
#define GRID 1024        // balanced single wave: each CTA handles ntiles/GRID tiles
#define MAX_BLOCKS 8192

__device__ float g_pen_part[MAX_BLOCKS];
__device__ int   g_ctr = 0;          // last-block-done counter (reset each replay)

#define LOG2E 1.4426950408889634f

// sigmoid via single HW MUFU tanh: sigma(x) = 0.5*tanh(x/2) + 0.5
__device__ __forceinline__ float fsig_times(float rbf, float x, float acc) {
    float t;
    asm("tanh.approx.f32 %0, %1;" : "=f"(t) : "f"(x * 0.5f));
    return fmaf(rbf, fmaf(t, 0.5f, 0.5f), acc);
}

__device__ __forceinline__ float fexp2(float x) {
    float r;
    asm("ex2.approx.f32 %0, %1;" : "=f"(r) : "f"(x));
    return r;
}

// Per-element packed coefficients (scale s=-0.5*log2e folded into A), 3 float4/elt:
//  p0 = {cx, cy, cz, w0}   p1 = {a00, a01, a02, a11}   p2 = {a12, a22, -, -}
// rbf = exp2( d^T a d + w0 ),  d = p - c,  w0 = log2|const|
__device__ __forceinline__ void compute_params(
    float4* sp, int ec,
    const float* __restrict__ constants,
    const float* __restrict__ centers,
    const float* __restrict__ radii,
    const float* __restrict__ rotations)
{
    int e = threadIdx.x;
    if (e < ec) {
        float ccx = centers[3*e+0];
        float ccy = centers[3*e+1];
        float ccz = centers[3*e+2];
        float cab = fabsf(constants[e]);
        float d0 = __fdividef(1.0f, fabsf(radii[3*e+0]) + 0.005f + 1e-8f);
        float d1 = __fdividef(1.0f, fabsf(radii[3*e+1]) + 0.005f + 1e-8f);
        float d2 = __fdividef(1.0f, fabsf(radii[3*e+2]) + 0.005f + 1e-8f);

        float sx, cx, sy, cy, sz, cz;
        __sincosf(rotations[3*e+0], &sx, &cx);
        __sincosf(rotations[3*e+1], &sy, &cy);
        __sincosf(rotations[3*e+2], &sz, &cz);

        float R00 = cz * cy;
        float R01 = cz * sy * sx - sz * cx;
        float R02 = cz * sy * cx + sz * sx;
        float R10 = sz * cy;
        float R11 = sz * sy * sx + cz * cx;
        float R12 = sz * sy * cx - cz * sx;
        float R20 = -sy;
        float R21 = cy * sx;
        float R22 = cy * cx;

        float c00 = R00*R00*d0 + R01*R01*d1 + R02*R02*d2;
        float c01 = R00*R10*d0 + R01*R11*d1 + R02*R12*d2;
        float c02 = R00*R20*d0 + R01*R21*d1 + R02*R22*d2;
        float c11 = R10*R10*d0 + R11*R11*d1 + R12*R12*d2;
        float c12 = R10*R20*d0 + R11*R21*d1 + R12*R22*d2;
        float c22 = R20*R20*d0 + R21*R21*d1 + R22*R22*d2;

        const float s = -0.5f * LOG2E;
        float w0 = __log2f(cab);

        sp[e*3 + 0] = make_float4(ccx, ccy, ccz, w0);
        sp[e*3 + 1] = make_float4(s*c00, s*c01, s*c02, s*c11);
        sp[e*3 + 2] = make_float4(s*c12, s*c22, 0.0f, 0.0f);
    }
}

__global__ void __launch_bounds__(BLK, 8) rbf_main(
    const float* __restrict__ wsp,
    const float4* __restrict__ act,
    const float* __restrict__ dists,
    float4* __restrict__ out,
    const float* __restrict__ constants,
    const float* __restrict__ centers,
    const float* __restrict__ radii,
    const float* __restrict__ rotations,
    int N, int ec, int out_size, int ntiles)
{
    __shared__ float4 sp[EC_MAX * 3];
    __shared__ float s_sum[PPB];
    __shared__ float4 s_acc[PPB];
    __shared__ float wpen[BLK / 32];
    __shared__ bool s_last;

    int tid = threadIdx.x;
    compute_params(sp, ec, constants, centers, radii, rotations);
    __syncthreads();

    int pt   = tid & (PPB - 1);          // 0..127: which point in the tile
    int half = tid >> 7;                 // 0 or 1: which element half
    int ehalf = ec >> 1;                 // 32
    int e0 = half * ehalf;
    const float4* cf0 = sp + e0 * 3;

    float pen = 0.0f;

    for (int tile = blockIdx.x; tile < ntiles; tile += GRID) {
        int n = tile * PPB + pt;
        bool valid = n < N;              // whole tile valid when N % PPB == 0

        float px=0, py=0, pz=0, ndl=0;
        if (valid) {
            px = wsp[3*n+0];
            py = wsp[3*n+1];
            pz = wsp[3*n+2];
            ndl = -dists[n] * LOG2E;     // alpha = 1 - exp2(relu(aw)*ndl)
        }

        float sum = 0.0f, ax = 0.0f, ay = 0.0f, az = 0.0f, aw = 0.0f;
        const float4* col = act + (size_t)e0 * N + n;
        const float4* cf  = cf0;

        if (valid) {
            #pragma unroll 2
            for (int e = 0; e < ehalf; ++e) {
                float4 p0 = cf[0];
                float4 p1 = cf[1];
                float4 p2 = cf[2];
                cf += 3;

                float4 a = __ldcs(col);
                col += N;

                float dx = px - p0.x, dy = py - p0.y, dz = pz - p0.z;
                float tx = fmaf(p1.x, dx, fmaf(p1.y, dy, p1.z * dz));
                float ty = fmaf(p1.y, dx, fmaf(p1.w, dy, p2.x * dz));
                float tz = fmaf(p1.z, dx, fmaf(p2.x, dy, p2.y * dz));
                float t  = fmaf(dx, tx, fmaf(dy, ty, fmaf(dz, tz, p0.w)));
                float rbf = fexp2(t);

                sum += rbf;
                pen += fmaxf(rbf - 0.01f, 0.0f);

                float alpha = 1.0f - fexp2(fmaxf(a.w, 0.0f) * ndl);
                ax = fsig_times(rbf, a.x, ax);
                ay = fsig_times(rbf, a.y, ay);
                az = fsig_times(rbf, a.z, az);
                aw = fmaf(rbf, alpha, aw);
            }
        }

        // high half publishes its partials; low half combines, normalizes, stores
        if (half == 1) {
            s_sum[pt] = sum;
            s_acc[pt] = make_float4(ax, ay, az, aw);
        }
        __syncthreads();
        if (half == 0 && valid) {
            float4 o = s_acc[pt];
            float st = sum + s_sum[pt];
            float winv = __fdividef(1.0f, st + 1e-6f);
            out[n] = make_float4((ax + o.x)*winv, (ay + o.y)*winv,
                                 (az + o.z)*winv, (aw + o.w)*winv);
        }
        __syncthreads();   // protect s_sum/s_acc reuse next tile
    }

    // block penalty reduction (accumulated over all tiles this CTA handled)
    #pragma unroll
    for (int off = 16; off; off >>= 1)
        pen += __shfl_xor_sync(0xffffffffu, pen, off);
    if ((tid & 31) == 0) wpen[tid >> 5] = pen;
    __syncthreads();
    if (tid == 0) {
        float s = 0.0f;
        #pragma unroll
        for (int w = 0; w < BLK / 32; ++w) s += wpen[w];
        g_pen_part[blockIdx.x] = s;
        __threadfence();
        int done = atomicAdd(&g_ctr, 1);
        s_last = (done == (int)gridDim.x - 1);
    }
    __syncthreads();

    // last finished block reduces all partials + bbox penalty, writes scalar,
    // resets counter for deterministic graph replay.
    if (s_last) {
        float s = 0.0f;
        for (int i = tid; i < (int)gridDim.x; i += BLK) s += g_pen_part[i];
        if (tid < ec) {
            float cx0 = centers[3*tid+0], cy0 = centers[3*tid+1], cz0 = centers[3*tid+2];
            float bp = fmaxf(cx0 - 0.6f, 0.0f) + fmaxf(-0.6f  - cx0, 0.0f)
                     + fmaxf(cy0 - 0.6f, 0.0f) + fmaxf(-0.6f  - cy0, 0.0f)
                     + fmaxf(cz0 - 0.6f, 0.0f) + fmaxf(-0.35f - cz0, 0.0f);
            s += bp * (float)N * 1000.0f;   // undo the 0.001/N scale below
        }
        #pragma unroll
        for (int off = 16; off; off >>= 1)
            s += __shfl_xor_sync(0xffffffffu, s, off);
        if ((tid & 31) == 0) wpen[tid >> 5] = s;
        __syncthreads();
        if (tid == 0) {
            float tot = 0.0f;
            #pragma unroll
            for (int w = 0; w < BLK / 32; ++w) tot += wpen[w];
            if (out_size > 4 * N)
                ((float*)out)[out_size - 1] = 0.001f * tot / (float)N;
            g_ctr = 0;
        }
    }
}

extern "C" void kernel_launch(void* const* d_in, const int* in_sizes, int n_in,
                              void* d_out, int out_size) {
    const float*  wsp       = (const float*)d_in[0];
    const float4* act       = (const float4*)d_in[1];
    const float*  dists     = (const float*)d_in[2];
    const float*  constants = (const float*)d_in[3];
    const float*  centers   = (const float*)d_in[4];
    const float*  radii     = (const float*)d_in[5];
    const float*  rotations = (const float*)d_in[6];

    int N  = in_sizes[0] / 3;
    int ec = in_sizes[3];
    if (ec > EC_MAX) ec = EC_MAX;

    int ntiles = (N + PPB - 1) / PPB;
    int grid = GRID < ntiles ? GRID : ntiles;
    rbf_main<<<grid, BLK>>>(wsp, act, dists, (float4*)d_out,
                            constants, centers, radii, rotations,
                            N, ec, out_size, ntiles);
}